// round 7
// baseline (speedup 1.0000x reference)
#include <cuda_runtime.h>
#include <cuda_fp16.h>
#include <math.h>

// ---------------------------------------------------------------------------
// Problem constants
// ---------------------------------------------------------------------------
#define B       16384
#define HID     512
#define NDETER  512
#define NGATE   1536
#define KIN     1084
#define KINP    1088          // KIN padded to /32
#define KOBS    5632
#define NSTATS  1024
#define OUTW    2560
#define LNEPS   1e-3f
#define UNIMIX  0.01f
#define LO_SCALE    2048.0f
#define LO_UNSCALE  (1.0f / 2048.0f)

// ---------------------------------------------------------------------------
// Scratch (device globals; no runtime allocation allowed)
// ---------------------------------------------------------------------------
__device__ float  g_xbuf[(size_t)B * HID];
__device__ float  g_ybuf[(size_t)B * HID];
__device__ float  g_gi  [(size_t)B * NGATE];
__device__ float  g_gh  [(size_t)B * NGATE];
// fp16 hi/lo planes: [hi(rows*K) | lo(rows*K)]
__device__ __half g_win [2 * (size_t)512  * KINP];
__device__ __half g_wih [2 * (size_t)1536 * 512];
__device__ __half g_whh [2 * (size_t)1536 * 512];
__device__ __half g_wobs[2 * (size_t)512  * KOBS];
__device__ __half g_wst [2 * (size_t)1024 * 512];
__device__ __half g_xin [2 * (size_t)B * KINP];
__device__ __half g_xq  [2 * (size_t)B * 512];
__device__ __half g_dq  [2 * (size_t)B * 512];
__device__ __half g_yin [2 * (size_t)B * KOBS];
__device__ __half g_yq  [2 * (size_t)B * 512];

// ---------------------------------------------------------------------------
// Helpers
// ---------------------------------------------------------------------------
__device__ __forceinline__ unsigned smem_u32(const void* p) {
    unsigned a;
    asm("{ .reg .u64 t; cvta.to.shared.u64 t, %1; cvt.u32.u64 %0, t; }"
        : "=r"(a) : "l"(p));
    return a;
}

#define MMA16816(acc, a, b0v, b1v)                                            \
    asm volatile(                                                             \
        "mma.sync.aligned.m16n8k16.row.col.f32.f16.f16.f32 "                  \
        "{%0,%1,%2,%3}, {%4,%5,%6,%7}, {%8,%9}, {%0,%1,%2,%3};"               \
        : "+f"((acc)[0]), "+f"((acc)[1]), "+f"((acc)[2]), "+f"((acc)[3])      \
        : "r"((a)[0]), "r"((a)[1]), "r"((a)[2]), "r"((a)[3]),                 \
          "r"(b0v), "r"(b1v))

#define LDMX4(r0, r1, r2, r3, addr)                                           \
    asm volatile("ldmatrix.sync.aligned.m8n8.x4.shared.b16 {%0,%1,%2,%3}, [%4];" \
        : "=r"(r0), "=r"(r1), "=r"(r2), "=r"(r3) : "r"(addr))

#define CP16(dst, srcp)                                                       \
    asm volatile("cp.async.cg.shared.global [%0], [%1], 16;"                  \
                 :: "r"(dst), "l"(srcp) : "memory")
#define CP_COMMIT() asm volatile("cp.async.commit_group;" ::: "memory")
#define CP_WAIT2()  asm volatile("cp.async.wait_group 2;" ::: "memory")

// ---------------------------------------------------------------------------
// fp16-split (Ootomo, scaled residual) HMMA GEMM on preconverted hi/lo planes:
//   C[M,N] = A[M,K] * W[N,K]^T (+ bias),  K % 32 == 0 (zero-padded upstream)
// acc0 += hi*hi;  acc1 += hi*lo + lo*hi;  C = acc0 + acc1/2048. fp32 acc.
// CTA 128x128, 8 warps (2Mx4N), warp 64x32, K-chunk 32.
// 4-stage cp.async pipeline, 48KB stage stride.
// Stage layout: Ah@0, Al@10240, Bh@20480, Bl@30720 (pitch 80 rows, 32 fp16).
// Numerically bit-identical to round 6 (same rn converts upstream, same
// accumulation order).
// ---------------------------------------------------------------------------
#define PITCH   80
#define AL_REL  10240u
#define BH_REL  20480u
#define STG     49152u
#define GEMM_SMEM (4 * 49152)

__global__ __launch_bounds__(256, 1)
void gemm_hmma(const __half* __restrict__ Apl, size_t AloOff,
               const __half* __restrict__ Wpl, size_t WloOff,
               const float* __restrict__ bias,
               float* __restrict__ C, int ldc, int K)
{
    extern __shared__ char smem[];
    const unsigned sb = smem_u32(smem);
    const int tid  = threadIdx.x;
    const int lane = tid & 31;
    const int wid  = tid >> 5;
    const int mW   = (wid >> 2) * 64;
    const int nW   = (wid & 3) * 32;
    const int mBase = blockIdx.y * 128;
    const int nBase = blockIdx.x * 128;

    float acc0[4][4][4];
    float acc1[4][4][4];
#pragma unroll
    for (int i = 0; i < 4; i++)
#pragma unroll
        for (int j = 0; j < 4; j++)
#pragma unroll
            for (int c = 0; c < 4; c++) { acc0[i][j][c] = 0.f; acc1[i][j][c] = 0.f; }

    // ---- cp.async mapping: thread -> (row = tid>>1, 32B half = tid&1) ----
    const int cprow = tid >> 1;
    const int cpel  = (tid & 1) * 16;           // halfs offset within 64B row
    const __half* pAh = Apl + (size_t)(mBase + cprow) * K + cpel;
    const __half* pAl = pAh + AloOff;
    const __half* pWh = Wpl + (size_t)(nBase + cprow) * K + cpel;
    const __half* pWl = pWh + WloOff;
    const unsigned dA = (unsigned)(cprow * PITCH + (tid & 1) * 32);

    auto cpa = [&](int k0, unsigned stg) {
        const unsigned d = sb + stg + dA;
        CP16(d,                pAh + k0); CP16(d + 16u,               pAh + k0 + 8);
        CP16(d + AL_REL,       pAl + k0); CP16(d + AL_REL + 16u,      pAl + k0 + 8);
        CP16(d + BH_REL,       pWh + k0); CP16(d + BH_REL + 16u,      pWh + k0 + 8);
        CP16(d + BH_REL + AL_REL, pWl + k0);
        CP16(d + BH_REL + AL_REL + 16u, pWl + k0 + 8);
    };

    // ---- ldmatrix bases (per-stage = + (it&3)*STG) ----
    const unsigned aOff = (unsigned)((mW + (lane & 15)) * PITCH + (lane >> 4) * 16);
    const unsigned bOff = BH_REL + (unsigned)((nW + (lane & 15)) * PITCH + (lane >> 4) * 16);

    const int nch = K >> 5;                      // K % 32 == 0, nch >= 16

    cpa(0,  0);       CP_COMMIT();
    cpa(32, STG);     CP_COMMIT();
    cpa(64, 2 * STG); CP_COMMIT();

    for (int it = 0; it < nch; ++it) {
        CP_WAIT2();
        __syncthreads();
        if (it + 3 < nch) cpa((it + 3) << 5, (unsigned)((it + 3) & 3) * STG);
        CP_COMMIT();

        const unsigned stgB = sb + (unsigned)(it & 3) * STG;
        const unsigned aB = stgB + aOff;
        const unsigned bB = stgB + bOff;

#pragma unroll
        for (int kk = 0; kk < 2; ++kk) {
            unsigned bH[4][2], bL[4][2];
#pragma unroll
            for (int np = 0; np < 2; ++np) {
                const unsigned bd = bB + (unsigned)(np * 16 * PITCH + kk * 32);
                unsigned r0, r1, r2, r3;
                LDMX4(r0, r1, r2, r3, bd);
                bH[2 * np][0] = r0; bH[2 * np][1] = r2;
                bH[2 * np + 1][0] = r1; bH[2 * np + 1][1] = r3;
                LDMX4(r0, r1, r2, r3, bd + AL_REL);
                bL[2 * np][0] = r0; bL[2 * np][1] = r2;
                bL[2 * np + 1][0] = r1; bL[2 * np + 1][1] = r3;
            }
            unsigned aH[2][4], aL[2][4];
            {
                const unsigned ad = aB + (unsigned)(kk * 32);
                LDMX4(aH[0][0], aH[0][1], aH[0][2], aH[0][3], ad);
                LDMX4(aL[0][0], aL[0][1], aL[0][2], aL[0][3], ad + AL_REL);
            }
#pragma unroll
            for (int mt = 0; mt < 4; ++mt) {
                const int cur = mt & 1, nxt = cur ^ 1;
                if (mt < 3) {
                    const unsigned ad = aB + (unsigned)((mt + 1) * 16 * PITCH + kk * 32);
                    LDMX4(aH[nxt][0], aH[nxt][1], aH[nxt][2], aH[nxt][3], ad);
                    LDMX4(aL[nxt][0], aL[nxt][1], aL[nxt][2], aL[nxt][3], ad + AL_REL);
                }
#pragma unroll
                for (int nt = 0; nt < 4; ++nt)
                    MMA16816(acc0[mt][nt], aH[cur], bH[nt][0], bH[nt][1]);
#pragma unroll
                for (int nt = 0; nt < 4; ++nt)
                    MMA16816(acc1[mt][nt], aH[cur], bL[nt][0], bL[nt][1]);
#pragma unroll
                for (int nt = 0; nt < 4; ++nt)
                    MMA16816(acc1[mt][nt], aL[cur], bH[nt][0], bH[nt][1]);
            }
        }
    }

    // ---- epilogue: C = acc0 + acc1/2048 (+bias) ----
    const int g = lane >> 2, t = lane & 3;
#pragma unroll
    for (int mt = 0; mt < 4; ++mt) {
#pragma unroll
        for (int nt = 0; nt < 4; ++nt) {
            const int row = mBase + mW + mt * 16 + g;
            const int col = nBase + nW + nt * 8 + t * 2;
            float bx = 0.f, by = 0.f;
            if (bias) { bx = bias[col]; by = bias[col + 1]; }
            float2 o0, o1;
            o0.x = fmaf(acc1[mt][nt][0], LO_UNSCALE, acc0[mt][nt][0]) + bx;
            o0.y = fmaf(acc1[mt][nt][1], LO_UNSCALE, acc0[mt][nt][1]) + by;
            o1.x = fmaf(acc1[mt][nt][2], LO_UNSCALE, acc0[mt][nt][2]) + bx;
            o1.y = fmaf(acc1[mt][nt][3], LO_UNSCALE, acc0[mt][nt][3]) + by;
            *(float2*)(C + (size_t)row * ldc + col)       = o0;
            *(float2*)(C + (size_t)(row + 8) * ldc + col) = o1;
        }
    }
}

// ---------------------------------------------------------------------------
// fp32 -> fp16 hi/lo plane converter.
// dst planes: hi at dstHi, lo at dstLo; row stride dstStride; writes `cols`
// columns starting at dstColOff; source has srcCols valid columns (zero fill
// beyond). cols % 4 == 0; all strides keep float4/__half2 alignment.
// ---------------------------------------------------------------------------
__global__ void conv_planes(const float* __restrict__ src, int srcStride, int srcCols,
                            __half* __restrict__ dstHi, __half* __restrict__ dstLo,
                            int dstStride, int dstColOff, int cols, int total)
{
    int i = blockIdx.x * blockDim.x + threadIdx.x;
    if (i >= total) return;
    const int cpr = cols >> 2;
    const int row = i / cpr;
    const int col = (i - row * cpr) << 2;
    float x0, x1, x2, x3;
    if (col + 4 <= srcCols) {
        float4 v = *(const float4*)(src + (size_t)row * srcStride + col);
        x0 = v.x; x1 = v.y; x2 = v.z; x3 = v.w;
    } else {
        const float* p = src + (size_t)row * srcStride;
        x0 = (col + 0 < srcCols) ? p[col + 0] : 0.f;
        x1 = (col + 1 < srcCols) ? p[col + 1] : 0.f;
        x2 = (col + 2 < srcCols) ? p[col + 2] : 0.f;
        x3 = (col + 3 < srcCols) ? p[col + 3] : 0.f;
    }
    __half2 h01 = __floats2half2_rn(x0, x1);
    __half2 h23 = __floats2half2_rn(x2, x3);
    float2 f01 = __half22float2(h01);
    float2 f23 = __half22float2(h23);
    __half2 l01 = __floats2half2_rn((x0 - f01.x) * LO_SCALE, (x1 - f01.y) * LO_SCALE);
    __half2 l23 = __floats2half2_rn((x2 - f23.x) * LO_SCALE, (x3 - f23.y) * LO_SCALE);
    const size_t o = (size_t)row * dstStride + dstColOff + col;
    *(__half2*)(dstHi + o)     = h01;
    *(__half2*)(dstHi + o + 2) = h23;
    *(__half2*)(dstLo + o)     = l01;
    *(__half2*)(dstLo + o + 2) = l23;
}

// ---------------------------------------------------------------------------
// LayerNorm(eps=1e-3) + SiLU -> fp16 hi/lo planes (rows of 512)
// ---------------------------------------------------------------------------
__device__ __forceinline__ float block_reduce_128(float v, float* sm)
{
#pragma unroll
    for (int o = 16; o > 0; o >>= 1) v += __shfl_xor_sync(0xffffffffu, v, o);
    int w = threadIdx.x >> 5;
    if ((threadIdx.x & 31) == 0) sm[w] = v;
    __syncthreads();
    float r = sm[0] + sm[1] + sm[2] + sm[3];
    __syncthreads();
    return r;
}

__global__ void ln_silu_kernel(const float* __restrict__ in,
                               __half* __restrict__ outHi, __half* __restrict__ outLo,
                               const float* __restrict__ g, const float* __restrict__ bb)
{
    __shared__ float sm[4];
    const int row = blockIdx.x;
    const float4 v = ((const float4*)(in + (size_t)row * HID))[threadIdx.x];
    float s = v.x + v.y + v.z + v.w;
    float mean = block_reduce_128(s, sm) * (1.f / HID);
    float dx = v.x - mean, dy = v.y - mean, dz = v.z - mean, dw = v.w - mean;
    float q = dx * dx + dy * dy + dz * dz + dw * dw;
    float var = block_reduce_128(q, sm) * (1.f / HID);
    float rs = rsqrtf(var + LNEPS);
    float4 gg = ((const float4*)g)[threadIdx.x];
    float4 bv = ((const float4*)bb)[threadIdx.x];
    float t0 = dx * rs * gg.x + bv.x;
    float t1 = dy * rs * gg.y + bv.y;
    float t2 = dz * rs * gg.z + bv.z;
    float t3 = dw * rs * gg.w + bv.w;
    float o0 = t0 / (1.f + expf(-t0));
    float o1 = t1 / (1.f + expf(-t1));
    float o2 = t2 / (1.f + expf(-t2));
    float o3 = t3 / (1.f + expf(-t3));
    __half2 h01 = __floats2half2_rn(o0, o1);
    __half2 h23 = __floats2half2_rn(o2, o3);
    float2 f01 = __half22float2(h01);
    float2 f23 = __half22float2(h23);
    __half2 l01 = __floats2half2_rn((o0 - f01.x) * LO_SCALE, (o1 - f01.y) * LO_SCALE);
    __half2 l23 = __floats2half2_rn((o2 - f23.x) * LO_SCALE, (o3 - f23.y) * LO_SCALE);
    const size_t o = (size_t)row * HID + threadIdx.x * 4;
    *(__half2*)(outHi + o)     = h01;
    *(__half2*)(outHi + o + 2) = h23;
    *(__half2*)(outLo + o)     = l01;
    *(__half2*)(outLo + o + 2) = l23;
}

// ---------------------------------------------------------------------------
// GRU gates -> deter into d_out cols [0,512) AND yin planes cols [0,512)
// ---------------------------------------------------------------------------
__device__ __forceinline__ float sigmoidf_(float x) { return 1.f / (1.f + expf(-x)); }

__global__ void gru_kernel(const float* __restrict__ gi, const float* __restrict__ gh,
                           const float* __restrict__ deter_old, float* __restrict__ out,
                           __half* __restrict__ yinHi, __half* __restrict__ yinLo)
{
    int idx = blockIdx.x * blockDim.x + threadIdx.x;
    int b = idx >> 9;
    int h = idx & 511;
    size_t base = (size_t)b * NGATE;
    float r = sigmoidf_(gi[base + h]        + gh[base + h]);
    float z = sigmoidf_(gi[base + 512 + h]  + gh[base + 512 + h]);
    float n = tanhf    (gi[base + 1024 + h] + r * gh[base + 1024 + h]);
    float d = (1.f - z) * n + z * deter_old[(size_t)b * NDETER + h];
    out[(size_t)b * OUTW + h] = d;
    __half hh = __float2half_rn(d);
    __half hl = __float2half_rn((d - __half2float(hh)) * LO_SCALE);
    yinHi[(size_t)b * KOBS + h] = hh;
    yinLo[(size_t)b * KOBS + h] = hl;
}

// ---------------------------------------------------------------------------
// Per-group-32 softmax -> unimix -> argmax one-hot (d_out cols [1536,2560))
// ---------------------------------------------------------------------------
__global__ void softmax_onehot_kernel(float* __restrict__ out)
{
    int gw   = (blockIdx.x * blockDim.x + threadIdx.x) >> 5;
    int lane = threadIdx.x & 31;
    int b    = gw >> 5;
    int grp  = gw & 31;
    float* row = out + (size_t)b * OUTW;
    float l = row[512 + grp * 32 + lane];
    float m = l;
#pragma unroll
    for (int o = 16; o > 0; o >>= 1) m = fmaxf(m, __shfl_xor_sync(0xffffffffu, m, o));
    float e = expf(l - m);
    float s = e;
#pragma unroll
    for (int o = 16; o > 0; o >>= 1) s += __shfl_xor_sync(0xffffffffu, s, o);
    float p = (1.f - UNIMIX) * (e / s) + UNIMIX / 32.f;
    float bp = p; int bi = lane;
#pragma unroll
    for (int o = 16; o > 0; o >>= 1) {
        float op = __shfl_xor_sync(0xffffffffu, bp, o);
        int   oi = __shfl_xor_sync(0xffffffffu, bi, o);
        if (op > bp || (op == bp && oi < bi)) { bp = op; bi = oi; }
    }
    row[1536 + grp * 32 + lane] = (lane == bi) ? 1.f : 0.f;
}

// ---------------------------------------------------------------------------
// Launch
// ---------------------------------------------------------------------------
static inline void conv(const float* src, int ss, int sc, __half* hi, __half* lo,
                        int ds, int off, int cols, int rows)
{
    int total = rows * (cols / 4);
    conv_planes<<<(total + 255) / 256, 256>>>(src, ss, sc, hi, lo, ds, off, cols, total);
}

extern "C" void kernel_launch(void* const* d_in, const int* in_sizes, int n_in,
                              void* d_out_, int out_size)
{
    const float* obs   = (const float*)d_in[0];
    const float* act   = (const float*)d_in[1];
    const float* stoch = (const float*)d_in[2];
    const float* deter = (const float*)d_in[3];
    const float* W_in  = (const float*)d_in[4];
    const float* gin   = (const float*)d_in[5];
    const float* bin   = (const float*)d_in[6];
    const float* W_ih  = (const float*)d_in[7];
    const float* W_hh  = (const float*)d_in[8];
    const float* b_ih  = (const float*)d_in[9];
    const float* b_hh  = (const float*)d_in[10];
    const float* W_obs = (const float*)d_in[11];
    const float* gobs  = (const float*)d_in[12];
    const float* bobs  = (const float*)d_in[13];
    const float* W_st  = (const float*)d_in[14];
    const float* b_st  = (const float*)d_in[15];
    float* out = (float*)d_out_;

    float *xbuf, *ybuf, *gi, *gh;
    __half *win, *wih, *whh, *wobs, *wst, *xin, *xq, *dq, *yin, *yq;
    cudaGetSymbolAddress((void**)&xbuf, g_xbuf);
    cudaGetSymbolAddress((void**)&ybuf, g_ybuf);
    cudaGetSymbolAddress((void**)&gi,   g_gi);
    cudaGetSymbolAddress((void**)&gh,   g_gh);
    cudaGetSymbolAddress((void**)&win,  g_win);
    cudaGetSymbolAddress((void**)&wih,  g_wih);
    cudaGetSymbolAddress((void**)&whh,  g_whh);
    cudaGetSymbolAddress((void**)&wobs, g_wobs);
    cudaGetSymbolAddress((void**)&wst,  g_wst);
    cudaGetSymbolAddress((void**)&xin,  g_xin);
    cudaGetSymbolAddress((void**)&xq,   g_xq);
    cudaGetSymbolAddress((void**)&dq,   g_dq);
    cudaGetSymbolAddress((void**)&yin,  g_yin);
    cudaGetSymbolAddress((void**)&yq,   g_yq);

    cudaFuncSetAttribute(gemm_hmma, cudaFuncAttributeMaxDynamicSharedMemorySize, GEMM_SMEM);

    const size_t Axin = (size_t)B * KINP,  Aq = (size_t)B * 512,  Ayin = (size_t)B * KOBS;
    const size_t Lwin = (size_t)512 * KINP, Lwih = (size_t)1536 * 512,
                 Lwhh = (size_t)1536 * 512, Lwobs = (size_t)512 * KOBS,
                 Lwst = (size_t)1024 * 512;

    // ---- weight planes (per-launch, deterministic) ----
    conv(W_in,  KIN, KIN, win,  win  + Lwin,  KINP, 0, KINP, 512);
    conv(W_ih,  512, 512, wih,  wih  + Lwih,  512,  0, 512,  1536);
    conv(W_hh,  512, 512, whh,  whh  + Lwhh,  512,  0, 512,  1536);
    conv(W_obs, KOBS, KOBS, wobs, wobs + Lwobs, KOBS, 0, KOBS, 512);
    conv(W_st,  512, 512, wst,  wst  + Lwst,  512,  0, 512,  1024);
    // ---- activation planes ----
    conv(stoch, 1024, 1024, xin, xin + Axin, KINP, 0,    1024, B);
    conv(act,   60,   60,   xin, xin + Axin, KINP, 1024, 64,   B);   // pads to 1088
    conv(deter, 512,  512,  dq,  dq  + Aq,   512,  0,    512,  B);
    conv(obs,   5120, 5120, yin, yin + Ayin, KOBS, 512,  5120, B);

    const int MT = B / 128;  // 128

    // 1) x_pre = xin @ W_in^T          (N=512, K=1088)
    gemm_hmma<<<dim3(4, MT), 256, GEMM_SMEM>>>(xin, Axin, win, Lwin, nullptr, xbuf, HID, KINP);
    // 2) x = silu(LN(x_pre)) -> planes
    ln_silu_kernel<<<B, 128>>>(xbuf, xq, xq + Aq, gin, bin);
    // 3) gi = x @ W_ih^T + b_ih        (N=1536, K=512)
    gemm_hmma<<<dim3(12, MT), 256, GEMM_SMEM>>>(xq, Aq, wih, Lwih, b_ih, gi, NGATE, 512);
    // 4) gh = deter @ W_hh^T + b_hh
    gemm_hmma<<<dim3(12, MT), 256, GEMM_SMEM>>>(dq, Aq, whh, Lwhh, b_hh, gh, NGATE, 512);
    // 5) GRU -> deter_new into d_out[:,0:512) and yin planes[:,0:512)
    gru_kernel<<<(B * NDETER) / 256, 256>>>(gi, gh, deter, out, yin, yin + Ayin);
    // 6) y_pre = yin @ W_obs^T         (N=512, K=5632)
    gemm_hmma<<<dim3(4, MT), 256, GEMM_SMEM>>>(yin, Ayin, wobs, Lwobs, nullptr, ybuf, HID, KOBS);
    // 7) y = silu(LN(y_pre)) -> planes
    ln_silu_kernel<<<B, 128>>>(ybuf, yq, yq + Aq, gobs, bobs);
    // 8) logits = y @ W_st^T + b_st -> d_out[:,512:1536)
    gemm_hmma<<<dim3(8, MT), 256, GEMM_SMEM>>>(yq, Aq, wst, Lwst, b_st, out + 512, OUTW, 512);
    // 9) softmax/unimix/argmax one-hot -> d_out[:,1536:2560)
    softmax_onehot_kernel<<<(B * 32 * 32) / 256, 256>>>(out);
}

// round 8
// speedup vs baseline: 1.2342x; 1.2342x over previous
#include <cuda_runtime.h>
#include <cuda_fp16.h>
#include <math.h>

// ---------------------------------------------------------------------------
// Problem constants
// ---------------------------------------------------------------------------
#define B       16384
#define HID     512
#define NDETER  512
#define NGATE   1536
#define KIN     1084
#define KOBS    5632
#define NSTATS  1024
#define OUTW    2560
#define LNEPS   1e-3f
#define UNIMIX  0.01f
#define LO_SCALE    2048.0f
#define LO_UNSCALE  (1.0f / 2048.0f)

// ---------------------------------------------------------------------------
// Scratch (device globals; no runtime allocation allowed)
// ---------------------------------------------------------------------------
__device__ float g_xbuf[(size_t)B * HID];
__device__ float g_gi  [(size_t)B * NGATE];
__device__ float g_gh  [(size_t)B * NGATE];
__device__ float g_ybuf[(size_t)B * HID];

// ---------------------------------------------------------------------------
// Helpers
// ---------------------------------------------------------------------------
__device__ __forceinline__ unsigned smem_u32(const void* p) {
    unsigned a;
    asm("{ .reg .u64 t; cvta.to.shared.u64 t, %1; cvt.u32.u64 %0, t; }"
        : "=r"(a) : "l"(p));
    return a;
}

#define MMA16816(acc, a, b0v, b1v)                                            \
    asm volatile(                                                             \
        "mma.sync.aligned.m16n8k16.row.col.f32.f16.f16.f32 "                  \
        "{%0,%1,%2,%3}, {%4,%5,%6,%7}, {%8,%9}, {%0,%1,%2,%3};"               \
        : "+f"((acc)[0]), "+f"((acc)[1]), "+f"((acc)[2]), "+f"((acc)[3])      \
        : "r"((a)[0]), "r"((a)[1]), "r"((a)[2]), "r"((a)[3]),                 \
          "r"(b0v), "r"(b1v))

#define LDMX4(r0, r1, r2, r3, addr)                                           \
    asm volatile("ldmatrix.sync.aligned.m8n8.x4.shared.b16 {%0,%1,%2,%3}, [%4];" \
        : "=r"(r0), "=r"(r1), "=r"(r2), "=r"(r3) : "r"(addr))

// ---------------------------------------------------------------------------
// fp16-split (Ootomo, scaled residual) HMMA GEMM:
//   C[M,N] = A[M,K] * W[N,K]^T (+ bias)
// x = hi + lo/2048 (fp16).  acc0 += hi*hi;  acc1 += hi*lo + lo*hi;
// C = acc0 + acc1/2048.  fp32 accumulators.
// CTA tile 128x128, K-chunk 32 fp32, **16 warps (4Mx4N), warp tile 32x32**.
// 2-stage smem pipeline, stage layout AH@0, AL@10240, BH@20480, BL@30720,
// pitch 80B, stage stride 64KB (addresses fold to baseReg + const).
// Per-output-element accumulation order identical to rounds 5/6 ->
// bit-identical results (rel_err must stay 9.778e-4).
// ---------------------------------------------------------------------------
#define BKF     32
#define PITCH   80
#define AL_REL  10240u
#define BH_REL  20480u
#define STAGE_STRIDE 65536u
#define GEMM_SMEM (2 * 65536)

__global__ __launch_bounds__(512, 1)
void gemm_hmma(const float* __restrict__ A1, int lda1, int K1,
               const float* __restrict__ A2, int lda2,
               const float* __restrict__ W, const float* __restrict__ bias,
               float* __restrict__ C, int ldc, int K)
{
    extern __shared__ char smem[];
    const unsigned sb = smem_u32(smem);
    const int tid  = threadIdx.x;
    const int lane = tid & 31;
    const int wid  = tid >> 5;              // 0..15
    const int mW   = (wid >> 2) * 32;       // 4 M-groups
    const int nW   = (wid & 3) * 32;        // 4 N-groups
    const int mBase = blockIdx.y * 128;
    const int nBase = blockIdx.x * 128;

    float acc0[2][4][4];   // hi*hi
    float acc1[2][4][4];   // hi*lo + lo*hi (scaled by 2048)
#pragma unroll
    for (int i = 0; i < 2; i++)
#pragma unroll
        for (int j = 0; j < 4; j++)
#pragma unroll
            for (int c = 0; c < 4; c++) { acc0[i][j][c] = 0.f; acc1[i][j][c] = 0.f; }

    // ---- hoisted global pointers: 2 A float4 + 2 W float4 per thread/chunk ----
    const int rowq = tid >> 3;             // 0..63
    const int c4b  = (tid & 7) * 4;        // k element offset
    const float* A2b = A2 ? A2 : A1;
    const int    ld2 = A2 ? lda2 : 0;
    const int    c4b2 = A2 ? c4b : 0;
    const float* pA1[2]; const float* pA2[2]; const float* pW[2];
#pragma unroll
    for (int q = 0; q < 2; ++q) {
        const int row = q * 64 + rowq;
        pA1[q] = A1  + (size_t)(mBase + row) * lda1 + c4b;
        pA2[q] = A2b + (size_t)(mBase + row) * ld2  + c4b2;
        pW[q]  = W   + (size_t)(nBase + row) * K    + c4b;
    }

    // ---- hoisted smem bases ----
    const unsigned stsBase0 = sb + (unsigned)(rowq * PITCH + (tid & 7) * 8);
    const unsigned stsBase1 = stsBase0 + STAGE_STRIDE;
    const unsigned aBase0 = sb + (unsigned)((mW + (lane & 15)) * PITCH + (lane >> 4) * 16);
    const unsigned aBase1 = aBase0 + STAGE_STRIDE;
    const unsigned bBase0 = sb + BH_REL
                          + (unsigned)((nW + (lane & 15)) * PITCH + (lane >> 4) * 16);
    const unsigned bBase1 = bBase0 + STAGE_STRIDE;

    const int nch = (K + BKF - 1) / BKF;

    float4 v[4];
    auto ldg_chunk = [&](int k0) {
        const bool seg1 = (k0 < K1);
        const int  kA   = seg1 ? k0 : k0 - K1;
        if (k0 + BKF <= K) {
#pragma unroll
            for (int q = 0; q < 2; ++q) {
                v[q]     = *(const float4*)((seg1 ? pA1[q] : pA2[q]) + kA);
                v[q + 2] = *(const float4*)(pW[q] + k0);
            }
        } else {
            const int rem = K - k0;
#pragma unroll
            for (int q = 0; q < 2; ++q) {
                float4 z = make_float4(0.f, 0.f, 0.f, 0.f);
                v[q]     = (c4b < rem) ? *(const float4*)((seg1 ? pA1[q] : pA2[q]) + kA) : z;
                v[q + 2] = (c4b < rem) ? *(const float4*)(pW[q] + k0) : z;
            }
        }
    };
    auto sts_chunk = [&](unsigned stsB) {
#pragma unroll
        for (int q = 0; q < 4; ++q) {
            const unsigned addr = stsB + (unsigned)((q & 1) * 64 * PITCH)
                                + (q < 2 ? 0u : BH_REL);
            const float4 x = v[q];
            __half2 h01 = __floats2half2_rn(x.x, x.y);
            __half2 h23 = __floats2half2_rn(x.z, x.w);
            float2 f01 = __half22float2(h01);
            float2 f23 = __half22float2(h23);
            __half2 l01 = __floats2half2_rn((x.x - f01.x) * LO_SCALE,
                                            (x.y - f01.y) * LO_SCALE);
            __half2 l23 = __floats2half2_rn((x.z - f23.x) * LO_SCALE,
                                            (x.w - f23.y) * LO_SCALE);
            unsigned uh0 = *(unsigned*)&h01, uh1 = *(unsigned*)&h23;
            unsigned ul0 = *(unsigned*)&l01, ul1 = *(unsigned*)&l23;
            asm volatile("st.shared.v2.b32 [%0], {%1,%2};"
                         :: "r"(addr), "r"(uh0), "r"(uh1) : "memory");
            asm volatile("st.shared.v2.b32 [%0], {%1,%2};"
                         :: "r"(addr + AL_REL), "r"(ul0), "r"(ul1) : "memory");
        }
    };

    ldg_chunk(0);
    sts_chunk(stsBase0);
    __syncthreads();

    for (int it = 0; it < nch; ++it) {
        const unsigned aB = (it & 1) ? aBase1 : aBase0;
        const unsigned bB = (it & 1) ? bBase1 : bBase0;
        if (it + 1 < nch) ldg_chunk((it + 1) * BKF);

#pragma unroll
        for (int kk = 0; kk < 2; ++kk) {
            // --- B fragments for this k16 (4 n8-tiles, hi+lo) ---
            unsigned bH[4][2], bL[4][2];
#pragma unroll
            for (int np = 0; np < 2; ++np) {
                const unsigned bd = bB + (unsigned)(np * 16 * PITCH + kk * 32);
                unsigned r0, r1, r2, r3;
                LDMX4(r0, r1, r2, r3, bd);
                bH[2 * np][0] = r0; bH[2 * np][1] = r2;
                bH[2 * np + 1][0] = r1; bH[2 * np + 1][1] = r3;
                LDMX4(r0, r1, r2, r3, bd + AL_REL);
                bL[2 * np][0] = r0; bL[2 * np][1] = r2;
                bL[2 * np + 1][0] = r1; bL[2 * np + 1][1] = r3;
            }
            // --- 2 m16-tiles: load A frags then 3 MMA passes ---
#pragma unroll
            for (int mt = 0; mt < 2; ++mt) {
                unsigned aH[4], aL[4];
                const unsigned ad = aB + (unsigned)(mt * 16 * PITCH + kk * 32);
                LDMX4(aH[0], aH[1], aH[2], aH[3], ad);
                LDMX4(aL[0], aL[1], aL[2], aL[3], ad + AL_REL);
#pragma unroll
                for (int nt = 0; nt < 4; ++nt)
                    MMA16816(acc0[mt][nt], aH, bH[nt][0], bH[nt][1]);
#pragma unroll
                for (int nt = 0; nt < 4; ++nt)
                    MMA16816(acc1[mt][nt], aH, bL[nt][0], bL[nt][1]);
#pragma unroll
                for (int nt = 0; nt < 4; ++nt)
                    MMA16816(acc1[mt][nt], aL, bH[nt][0], bH[nt][1]);
            }
        }

        if (it + 1 < nch) sts_chunk((it & 1) ? stsBase0 : stsBase1);
        __syncthreads();
    }

    // ---- epilogue: C = acc0 + acc1/2048 (+bias) ----
    const int g = lane >> 2, t = lane & 3;
#pragma unroll
    for (int mt = 0; mt < 2; ++mt) {
#pragma unroll
        for (int nt = 0; nt < 4; ++nt) {
            const int row = mBase + mW + mt * 16 + g;
            const int col = nBase + nW + nt * 8 + t * 2;
            float bx = 0.f, by = 0.f;
            if (bias) { bx = bias[col]; by = bias[col + 1]; }
            float2 o0, o1;
            o0.x = fmaf(acc1[mt][nt][0], LO_UNSCALE, acc0[mt][nt][0]) + bx;
            o0.y = fmaf(acc1[mt][nt][1], LO_UNSCALE, acc0[mt][nt][1]) + by;
            o1.x = fmaf(acc1[mt][nt][2], LO_UNSCALE, acc0[mt][nt][2]) + bx;
            o1.y = fmaf(acc1[mt][nt][3], LO_UNSCALE, acc0[mt][nt][3]) + by;
            *(float2*)(C + (size_t)row * ldc + col)       = o0;
            *(float2*)(C + (size_t)(row + 8) * ldc + col) = o1;
        }
    }
}

// ---------------------------------------------------------------------------
// LayerNorm(eps=1e-3) + SiLU (rows of 512; 128 threads/row)
// ---------------------------------------------------------------------------
__device__ __forceinline__ float block_reduce_128(float v, float* sm)
{
#pragma unroll
    for (int o = 16; o > 0; o >>= 1) v += __shfl_xor_sync(0xffffffffu, v, o);
    int w = threadIdx.x >> 5;
    if ((threadIdx.x & 31) == 0) sm[w] = v;
    __syncthreads();
    float r = sm[0] + sm[1] + sm[2] + sm[3];
    __syncthreads();
    return r;
}

__global__ void ln_silu_kernel(const float* __restrict__ in, float* __restrict__ out,
                               const float* __restrict__ g, const float* __restrict__ bb)
{
    __shared__ float sm[4];
    const int row = blockIdx.x;
    const float4 v = ((const float4*)(in + (size_t)row * HID))[threadIdx.x];
    float s = v.x + v.y + v.z + v.w;
    float mean = block_reduce_128(s, sm) * (1.f / HID);
    float dx = v.x - mean, dy = v.y - mean, dz = v.z - mean, dw = v.w - mean;
    float q = dx * dx + dy * dy + dz * dz + dw * dw;
    float var = block_reduce_128(q, sm) * (1.f / HID);
    float rs = rsqrtf(var + LNEPS);
    float4 gg = ((const float4*)g)[threadIdx.x];
    float4 bv = ((const float4*)bb)[threadIdx.x];
    float t0 = dx * rs * gg.x + bv.x;
    float t1 = dy * rs * gg.y + bv.y;
    float t2 = dz * rs * gg.z + bv.z;
    float t3 = dw * rs * gg.w + bv.w;
    float4 o;
    o.x = t0 / (1.f + expf(-t0));
    o.y = t1 / (1.f + expf(-t1));
    o.z = t2 / (1.f + expf(-t2));
    o.w = t3 / (1.f + expf(-t3));
    ((float4*)(out + (size_t)row * HID))[threadIdx.x] = o;
}

// ---------------------------------------------------------------------------
// GRU gates (torch order r,z,n) -> deter into d_out cols [0,512)
// ---------------------------------------------------------------------------
__device__ __forceinline__ float sigmoidf_(float x) { return 1.f / (1.f + expf(-x)); }

__global__ void gru_kernel(const float* __restrict__ gi, const float* __restrict__ gh,
                           const float* __restrict__ deter_old, float* __restrict__ out)
{
    int idx = blockIdx.x * blockDim.x + threadIdx.x;
    int b = idx >> 9;
    int h = idx & 511;
    size_t base = (size_t)b * NGATE;
    float r = sigmoidf_(gi[base + h]        + gh[base + h]);
    float z = sigmoidf_(gi[base + 512 + h]  + gh[base + 512 + h]);
    float n = tanhf    (gi[base + 1024 + h] + r * gh[base + 1024 + h]);
    float d = (1.f - z) * n + z * deter_old[(size_t)b * NDETER + h];
    out[(size_t)b * OUTW + h] = d;
}

// ---------------------------------------------------------------------------
// Per-group-32 softmax -> unimix -> argmax one-hot (d_out cols [1536,2560))
// ---------------------------------------------------------------------------
__global__ void softmax_onehot_kernel(float* __restrict__ out)
{
    int gw   = (blockIdx.x * blockDim.x + threadIdx.x) >> 5;
    int lane = threadIdx.x & 31;
    int b    = gw >> 5;
    int grp  = gw & 31;
    float* row = out + (size_t)b * OUTW;
    float l = row[512 + grp * 32 + lane];
    float m = l;
#pragma unroll
    for (int o = 16; o > 0; o >>= 1) m = fmaxf(m, __shfl_xor_sync(0xffffffffu, m, o));
    float e = expf(l - m);
    float s = e;
#pragma unroll
    for (int o = 16; o > 0; o >>= 1) s += __shfl_xor_sync(0xffffffffu, s, o);
    float p = (1.f - UNIMIX) * (e / s) + UNIMIX / 32.f;
    float bp = p; int bi = lane;
#pragma unroll
    for (int o = 16; o > 0; o >>= 1) {
        float op = __shfl_xor_sync(0xffffffffu, bp, o);
        int   oi = __shfl_xor_sync(0xffffffffu, bi, o);
        if (op > bp || (op == bp && oi < bi)) { bp = op; bi = oi; }
    }
    row[1536 + grp * 32 + lane] = (lane == bi) ? 1.f : 0.f;
}

// ---------------------------------------------------------------------------
// Launch
// ---------------------------------------------------------------------------
extern "C" void kernel_launch(void* const* d_in, const int* in_sizes, int n_in,
                              void* d_out_, int out_size)
{
    const float* obs   = (const float*)d_in[0];
    const float* act   = (const float*)d_in[1];
    const float* stoch = (const float*)d_in[2];
    const float* deter = (const float*)d_in[3];
    const float* W_in  = (const float*)d_in[4];
    const float* gin   = (const float*)d_in[5];
    const float* bin   = (const float*)d_in[6];
    const float* W_ih  = (const float*)d_in[7];
    const float* W_hh  = (const float*)d_in[8];
    const float* b_ih  = (const float*)d_in[9];
    const float* b_hh  = (const float*)d_in[10];
    const float* W_obs = (const float*)d_in[11];
    const float* gobs  = (const float*)d_in[12];
    const float* bobs  = (const float*)d_in[13];
    const float* W_st  = (const float*)d_in[14];
    const float* b_st  = (const float*)d_in[15];
    float* out = (float*)d_out_;

    float *xbuf, *gi, *gh, *ybuf;
    cudaGetSymbolAddress((void**)&xbuf, g_xbuf);
    cudaGetSymbolAddress((void**)&gi,   g_gi);
    cudaGetSymbolAddress((void**)&gh,   g_gh);
    cudaGetSymbolAddress((void**)&ybuf, g_ybuf);

    cudaFuncSetAttribute(gemm_hmma, cudaFuncAttributeMaxDynamicSharedMemorySize, GEMM_SMEM);

    const int MT = B / 128;  // 128

    // 1) x_pre = [stoch | actions] @ W_in^T      (N=512, K=1084, K1=1024)
    gemm_hmma<<<dim3(HID / 128, MT), 512, GEMM_SMEM>>>(
        stoch, 1024, 1024, act, 60, W_in, nullptr, xbuf, HID, KIN);
    // 2) x = silu(LN(x_pre))
    ln_silu_kernel<<<B, 128>>>(xbuf, xbuf, gin, bin);
    // 3) gi = x @ W_ih^T + b_ih                  (N=1536, K=512)
    gemm_hmma<<<dim3(NGATE / 128, MT), 512, GEMM_SMEM>>>(
        xbuf, HID, HID, nullptr, 0, W_ih, b_ih, gi, NGATE, HID);
    // 4) gh = deter @ W_hh^T + b_hh
    gemm_hmma<<<dim3(NGATE / 128, MT), 512, GEMM_SMEM>>>(
        deter, NDETER, NDETER, nullptr, 0, W_hh, b_hh, gh, NGATE, NDETER);
    // 5) GRU -> deter_new in d_out[:, 0:512)
    gru_kernel<<<(B * NDETER) / 256, 256>>>(gi, gh, deter, out);
    // 6) y_pre = [deter_new | obs_enc] @ W_obs^T (N=512, K=5632, K1=512)
    gemm_hmma<<<dim3(HID / 128, MT), 512, GEMM_SMEM>>>(
        out, OUTW, NDETER, obs, 5120, W_obs, nullptr, ybuf, HID, KOBS);
    // 7) y = silu(LN(y_pre))
    ln_silu_kernel<<<B, 128>>>(ybuf, ybuf, gobs, bobs);
    // 8) logits = y @ W_stats^T + b_stats -> d_out[:, 512:1536)
    gemm_hmma<<<dim3(NSTATS / 128, MT), 512, GEMM_SMEM>>>(
        ybuf, HID, HID, nullptr, 0, W_st, b_st, out + 512, OUTW, HID);
    // 9) softmax/unimix/argmax one-hot -> d_out[:, 1536:2560)
    softmax_onehot_kernel<<<(B * 32 * 32) / 256, 256>>>(out);
}